// round 1
// baseline (speedup 1.0000x reference)
#include <cuda_runtime.h>

#define IN_DIM 128
#define HIDD   128
#define OUTD   40
#define MAXN   50000
#define MAXE   800000

// ---------------- scratch (device globals: allocation-free) ----------------
static __device__ float g_xw[MAXN * HIDD];   // x @ W1
static __device__ float g_h [MAXN * HIDD];   // layer-1 aggregated output
static __device__ float g_hw[MAXN * OUTD];   // h @ W2
static __device__ float g_deg [MAXN];
static __device__ float g_dinv[MAXN];
static __device__ int   g_is64;              // edge_index dtype flag

// ---------------- edge-index dtype detection ----------------
// If int64: every odd 32-bit word (hi word of a small nonneg value) is 0.
// If int32: odd positions are random node ids in [0, N) -> ~surely nonzero.
__global__ void detect_kernel(const int* __restrict__ ei, int twoE) {
    __shared__ int s_any;
    if (threadIdx.x == 0) s_any = 0;
    __syncthreads();
    int lim = twoE < 8192 ? twoE : 8192;
    for (int i = 1 + 2 * (int)threadIdx.x; i < lim; i += 2 * (int)blockDim.x) {
        if (ei[i] != 0) s_any = 1;
    }
    __syncthreads();
    if (threadIdx.x == 0) g_is64 = (s_any == 0) ? 1 : 0;
}

__device__ __forceinline__ int get_idx(const void* ei, long long pos, int is64) {
    return is64 ? (int)((const long long*)ei)[pos]
                : ((const int*)ei)[pos];
}

// ---------------- init: deg=1 (self loop), zero h, zero out ----------------
__global__ void init_kernel(float* __restrict__ out, int N) {
    int i = blockIdx.x * blockDim.x + threadIdx.x;
    if (i < N * HIDD) g_h[i] = 0.0f;
    if (i < N * OUTD) out[i] = 0.0f;
    if (i < N)        g_deg[i] = 1.0f;
}

__global__ void deg_kernel(const void* __restrict__ ei, int E) {
    int e = blockIdx.x * blockDim.x + threadIdx.x;
    if (e >= E) return;
    int is64 = g_is64;
    int d = get_idx(ei, (long long)E + e, is64);
    atomicAdd(&g_deg[d], 1.0f);
}

__global__ void dinv_kernel(int N) {
    int i = blockIdx.x * blockDim.x + threadIdx.x;
    if (i < N) {
        float dg = g_deg[i];
        g_dinv[i] = dg > 0.0f ? rsqrtf(dg) : 0.0f;
    }
}

// ---------------- tiled fp32 GEMM: C[M,BN] = A[M,K] @ B[K,BN] ----------------
// grid.x over M tiles only (BN == full output width).
template <int BM, int BN, int BK, int TM, int TN>
__global__ void gemm_kernel(const float* __restrict__ A,
                            const float* __restrict__ B,
                            float* __restrict__ C, int M, int K) {
    constexpr int NT  = (BM / TM) * (BN / TN);
    constexpr int LDA = BM + 4;                 // padded to dodge bank conflicts
    __shared__ float As[BK * LDA];              // transposed: As[k][row]
    __shared__ float Bs[BK * BN];               // Bs[k][col]

    const int tid = threadIdx.x;
    const int tx  = tid % (BN / TN);
    const int ty  = tid / (BN / TN);
    const int row0 = blockIdx.x * BM;

    float acc[TM][TN];
#pragma unroll
    for (int i = 0; i < TM; i++)
#pragma unroll
        for (int j = 0; j < TN; j++) acc[i][j] = 0.0f;

    for (int k0 = 0; k0 < K; k0 += BK) {
        for (int idx = tid; idx < BM * BK; idx += NT) {
            int r = idx / BK, kk = idx % BK;
            int gr = row0 + r;
            As[kk * LDA + r] = (gr < M) ? A[(size_t)gr * K + k0 + kk] : 0.0f;
        }
        for (int idx = tid; idx < BK * BN; idx += NT) {
            int kk = idx / BN, c = idx % BN;
            Bs[kk * BN + c] = B[(size_t)(k0 + kk) * BN + c];
        }
        __syncthreads();
#pragma unroll
        for (int kk = 0; kk < BK; kk++) {
            float a[TM], b[TN];
#pragma unroll
            for (int i = 0; i < TM; i++) a[i] = As[kk * LDA + ty * TM + i];
#pragma unroll
            for (int j = 0; j < TN; j++) b[j] = Bs[kk * BN + tx * TN + j];
#pragma unroll
            for (int i = 0; i < TM; i++)
#pragma unroll
                for (int j = 0; j < TN; j++) acc[i][j] += a[i] * b[j];
        }
        __syncthreads();
    }

#pragma unroll
    for (int i = 0; i < TM; i++) {
        int gr = row0 + ty * TM + i;
        if (gr < M) {
#pragma unroll
            for (int j = 0; j < TN; j++)
                C[(size_t)gr * BN + tx * TN + j] = acc[i][j];
        }
    }
}

// ---------------- edge aggregation: out[dst] += norm * feat[src] ----------------
// W floats per edge, one float4 + one red.v4 per thread slot.
template <int W>
__global__ void agg_kernel(const float* __restrict__ feat,
                           const void* __restrict__ ei,
                           float* __restrict__ outp, int E) {
    constexpr int SL = W / 4;
    int t = blockIdx.x * blockDim.x + threadIdx.x;
    int e = t / SL;
    int p = t - e * SL;
    if (e >= E) return;
    int is64 = g_is64;
    int s = get_idx(ei, e, is64);
    int d = get_idx(ei, (long long)E + e, is64);
    float nm = g_dinv[s] * g_dinv[d];
    float4 v = *(const float4*)(feat + (size_t)s * W + p * 4);
    float* addr = outp + (size_t)d * W + p * 4;
    asm volatile("red.global.add.v4.f32 [%0], {%1,%2,%3,%4};"
                 :: "l"(__cvta_generic_to_global(addr)),
                    "f"(v.x * nm), "f"(v.y * nm), "f"(v.z * nm), "f"(v.w * nm)
                 : "memory");
}

// ---------------- layer-1 epilogue: self-loop term + bias + ReLU ----------------
__global__ void epi1_kernel(const float* __restrict__ b1, int N) {
    int idx = blockIdx.x * blockDim.x + threadIdx.x;
    if (idx >= N * HIDD) return;
    int r = idx >> 7;        // / 128
    int c = idx & 127;
    float di = g_dinv[r];
    float v = g_h[idx] + g_xw[idx] * di * di + b1[c];
    g_h[idx] = fmaxf(v, 0.0f);
}

// ---------------- layer-2 epilogue: self-loop + bias + softmax (in-place) ----------------
__global__ void softmax_kernel(float* __restrict__ out,
                               const float* __restrict__ b2, int N) {
    int r = blockIdx.x * blockDim.x + threadIdx.x;
    if (r >= N) return;
    float di = g_dinv[r];
    float d2 = di * di;
    float v[OUTD];
    const float4* orow = (const float4*)(out + (size_t)r * OUTD);
    const float4* hrow = (const float4*)(g_hw + (size_t)r * OUTD);
    float mx = -1e30f;
#pragma unroll
    for (int q = 0; q < OUTD / 4; q++) {
        float4 a = orow[q];
        float4 b = hrow[q];
        v[4 * q + 0] = a.x + b.x * d2 + b2[4 * q + 0];
        v[4 * q + 1] = a.y + b.y * d2 + b2[4 * q + 1];
        v[4 * q + 2] = a.z + b.z * d2 + b2[4 * q + 2];
        v[4 * q + 3] = a.w + b.w * d2 + b2[4 * q + 3];
    }
#pragma unroll
    for (int j = 0; j < OUTD; j++) mx = fmaxf(mx, v[j]);
    float sum = 0.0f;
#pragma unroll
    for (int j = 0; j < OUTD; j++) {
        v[j] = __expf(v[j] - mx);
        sum += v[j];
    }
    float inv = 1.0f / sum;
    float4* ow = (float4*)(out + (size_t)r * OUTD);
#pragma unroll
    for (int q = 0; q < OUTD / 4; q++) {
        float4 w;
        w.x = v[4 * q + 0] * inv;
        w.y = v[4 * q + 1] * inv;
        w.z = v[4 * q + 2] * inv;
        w.w = v[4 * q + 3] * inv;
        ow[q] = w;
    }
}

// ---------------- launch ----------------
extern "C" void kernel_launch(void* const* d_in, const int* in_sizes, int n_in,
                              void* d_out, int out_size) {
    const float* x  = (const float*)d_in[0];
    const void*  ei = d_in[1];
    const float* W1 = (const float*)d_in[2];
    const float* b1 = (const float*)d_in[3];
    const float* W2 = (const float*)d_in[4];
    const float* b2 = (const float*)d_in[5];
    float* out = (float*)d_out;

    int N = in_sizes[0] / IN_DIM;
    int E = in_sizes[1] / 2;

    float *xw, *h, *hw;
    cudaGetSymbolAddress((void**)&xw, g_xw);
    cudaGetSymbolAddress((void**)&h,  g_h);
    cudaGetSymbolAddress((void**)&hw, g_hw);

    detect_kernel<<<1, 256>>>((const int*)ei, 2 * E);
    init_kernel<<<(N * HIDD + 255) / 256, 256>>>(out, N);
    deg_kernel<<<(E + 255) / 256, 256>>>(ei, E);
    dinv_kernel<<<(N + 255) / 256, 256>>>(N);

    // layer 1: xw = x @ W1 ; h = scatter(norm * xw[src]) ; h = relu(h + self + b1)
    gemm_kernel<128, 128, 16, 8, 8><<<(N + 127) / 128, 256>>>(x, W1, xw, N, IN_DIM);
    {
        long long tot = (long long)E * (HIDD / 4);
        agg_kernel<HIDD><<<(unsigned)((tot + 255) / 256), 256>>>(xw, ei, h, E);
    }
    epi1_kernel<<<(N * HIDD + 255) / 256, 256>>>(b1, N);

    // layer 2: hw = h @ W2 ; out = scatter(norm * hw[src]) ; softmax(out + self + b2)
    gemm_kernel<128, 40, 16, 8, 5><<<(N + 127) / 128, 128>>>(h, W2, hw, N, HIDD);
    {
        long long tot = (long long)E * (OUTD / 4);
        agg_kernel<OUTD><<<(unsigned)((tot + 255) / 256), 256>>>(hw, ei, out, E);
    }
    softmax_kernel<<<(N + 255) / 256, 256>>>(out, b2, N);
}